// round 6
// baseline (speedup 1.0000x reference)
#include <cuda_runtime.h>
#include <cuda_fp16.h>
#include <mma.h>
#include <math.h>
#include <stdint.h>

using namespace nvcuda;

#define NN      2048
#define GG      32
#define NPG     64
#define EE      16384
#define EPG     512
#define HID     256
#define NH      8
#define HD      32
#define EF      16
#define SCALE_F 0.17677669529663687f   // 1/sqrt(32)

// ---------------- scratch (device globals, no runtime allocation) ----------
__device__ __align__(32) __half g_nodes16[NN * HID];
__device__ __align__(32) __half g_wT16[1024 * HID];   // rows 0-767: Wq|Wk|Wv cols, 768-1023: Wo cols (K contiguous)
__device__ __align__(32) __half g_attn16[NN * HID];
__device__ float g_q[NN * HID];
__device__ float g_k[NN * HID];
__device__ float g_v[NN * HID];

// Smem geometry: A tile only (B comes straight from global/L1)
static constexpr int LDA_S = 264;     // halves, pad 8
static constexpr int LDC_S = 132;     // floats, pad 4 (epilogue reuses the same buffer)

// ---------------------------------------------------------------------------
// Convert + transpose kernel.
// Blocks 0..255: transpose-convert 32x32 weight tiles into g_wT16 (n-major).
// Blocks 256..511: elementwise convert nodes -> g_nodes16.
// ---------------------------------------------------------------------------
__global__ void __launch_bounds__(256) cvt_kernel(
    const float* __restrict__ nodes,
    const float* __restrict__ Wq, const float* __restrict__ Wk,
    const float* __restrict__ Wv, const float* __restrict__ Wo)
{
    const int bx = blockIdx.x;
    const int tx = threadIdx.x;   // 0..31
    const int ty = threadIdx.y;   // 0..7
    if (bx < 256) {
        const int n0 = (bx & 31) * 32;
        const int k0 = (bx >> 5) * 32;
        __shared__ float s[32][33];
        const int mat  = n0 >> 8;
        const int col0 = n0 & 255;
        const float* W = (mat == 0) ? Wq : (mat == 1) ? Wk : (mat == 2) ? Wv : Wo;
#pragma unroll
        for (int j = 0; j < 4; j++) {
            const int k = k0 + ty + j * 8;
            s[ty + j * 8][tx] = W[k * 256 + col0 + tx];
        }
        __syncthreads();
#pragma unroll
        for (int j = 0; j < 4; j++) {
            const int n = n0 + ty + j * 8;
            g_wT16[n * 256 + k0 + tx] = __float2half(s[tx][ty + j * 8]);
        }
    } else {
        const int b   = bx - 256;
        const int tid = ty * 32 + tx;
#pragma unroll
        for (int r = 0; r < 2; r++) {
            const int i4 = b * 512 + r * 256 + tid;
            float4 v = ((const float4*)nodes)[i4];
            ((__half2*)g_nodes16)[i4 * 2 + 0] = __floats2half2_rn(v.x, v.y);
            ((__half2*)g_nodes16)[i4 * 2 + 1] = __floats2half2_rn(v.z, v.w);
        }
    }
}

// ---------------------------------------------------------------------------
// HMMA GEMM tile: C[m0:m0+64, 0:128] = A16[m0:m0+64, :] @ B16[wrow0:wrow0+128, :]^T + bias
// A staged in smem (34KB); B fragments loaded DIRECTLY from global (L1/L2-hot
// weights, col_major, ld=256). 8 warps in a 2x4 grid, each 32x32 via 2x2 frags.
// ---------------------------------------------------------------------------
__global__ void __launch_bounds__(256) gemm_hmma_kernel(
    const float* __restrict__ bq, const float* __restrict__ bk,
    const float* __restrict__ bv, const float* __restrict__ bo,
    float* __restrict__ outp, int pass)
{
    // pass 0: QKV (grid y=0..5), pass 1: out-proj (grid y=0..1)
    const int m0 = blockIdx.x * 64;
    const int nb = blockIdx.y * 128;
    const __half* Asrc;
    const float* bias;
    float* C;
    int wrow0;
    if (pass == 0) {
        const int which = nb >> 8;
        const int colin = nb & 255;
        Asrc  = g_nodes16;
        wrow0 = nb;
        C     = ((which == 0) ? g_q : (which == 1) ? g_k : g_v) + colin;
        bias  = ((which == 0) ? bq : (which == 1) ? bk : bv) + colin;
    } else {
        Asrc  = g_attn16;
        wrow0 = 768 + nb;
        C     = outp + nb;
        bias  = bo + nb;
    }

    __shared__ __align__(32) char smem[64 * LDA_S * 2];   // 33792 B
    __half* As = (__half*)smem;                           // [64][264]

    const int tid = threadIdx.x;
    const int wid = tid >> 5;
    const int wr  = wid >> 2;     // 0..1
    const int wc  = wid & 3;      // 0..3

    // ---- stage A (64x256) ----
    {
        const uint4* Ag = (const uint4*)(Asrc + m0 * 256);
#pragma unroll
        for (int i = tid; i < 2048; i += 256) {
            const int r = i >> 5, c = i & 31;
            *(uint4*)&As[r * LDA_S + c * 8] = Ag[r * 32 + c];
        }
    }
    __syncthreads();

    wmma::fragment<wmma::accumulator, 16, 16, 16, float> fc[2][2];
#pragma unroll
    for (int i = 0; i < 2; i++)
#pragma unroll
        for (int j = 0; j < 2; j++) wmma::fill_fragment(fc[i][j], 0.0f);

    const __half* Bg = g_wT16 + (wrow0 + wc * 32) * 256;

#pragma unroll
    for (int k0 = 0; k0 < 256; k0 += 16) {
        wmma::fragment<wmma::matrix_a, 16, 16, 16, __half, wmma::row_major> fa[2];
        wmma::fragment<wmma::matrix_b, 16, 16, 16, __half, wmma::col_major> fb[2];
#pragma unroll
        for (int i = 0; i < 2; i++)
            wmma::load_matrix_sync(fa[i], &As[(wr * 32 + i * 16) * LDA_S + k0], LDA_S);
#pragma unroll
        for (int j = 0; j < 2; j++)
            wmma::load_matrix_sync(fb[j], Bg + (j * 16) * 256 + k0, 256);
#pragma unroll
        for (int i = 0; i < 2; i++)
#pragma unroll
            for (int j = 0; j < 2; j++)
                wmma::mma_sync(fc[i][j], fa[i], fb[j], fc[i][j]);
    }
    __syncthreads();   // done with As; reuse buffer for the epilogue

    float* Cs = (float*)smem;     // [64][132] = 33792 B
#pragma unroll
    for (int i = 0; i < 2; i++)
#pragma unroll
        for (int j = 0; j < 2; j++)
            wmma::store_matrix_sync(&Cs[(wr * 32 + i * 16) * LDC_S + wc * 32 + j * 16],
                                    fc[i][j], LDC_S, wmma::mem_row_major);
    __syncthreads();

    // ---- bias add + vectorized store: 64 rows x 32 float4 ----
#pragma unroll
    for (int i = tid; i < 2048; i += 256) {
        const int r = i >> 5, c4 = (i & 31) * 4;
        float4 v = *(float4*)&Cs[r * LDC_S + c4];
        v.x += bias[c4 + 0];
        v.y += bias[c4 + 1];
        v.z += bias[c4 + 2];
        v.w += bias[c4 + 3];
        *(float4*)&C[(m0 + r) * 256 + c4] = v;
    }
}

// ---------------------------------------------------------------------------
// K2: per-(graph, head) attention with in-block edge bias (fp32 math,
// fp16 output for the HMMA out projection).
// ---------------------------------------------------------------------------
__global__ void __launch_bounds__(128) attn_kernel(
    const int* __restrict__ senders,
    const int* __restrict__ receivers,
    const float* __restrict__ edges,
    const float* __restrict__ We,
    const float* __restrict__ be)
{
    const int g = blockIdx.x >> 3;
    const int h = blockIdx.x & 7;
    const int tid = threadIdx.x;

    __shared__ float qs[64][33];
    __shared__ float ks[64][33];
    __shared__ float vs[64][33];
    __shared__ float sc[64][65];
    __shared__ float eb[EPG];

    for (int idx = tid; idx < 64 * 32; idx += 128) {
        const int r = idx >> 5;
        const int c = idx & 31;
        const int ga = (g * 64 + r) * 256 + h * 32 + c;
        qs[r][c] = g_q[ga];
        ks[r][c] = g_k[ga];
        vs[r][c] = g_v[ga];
    }

    for (int e = tid; e < EPG; e += 128) {
        const float* ef = &edges[(g * EPG + e) * EF];
        float s = be[h];
#pragma unroll
        for (int f = 0; f < EF; f++) s = fmaf(ef[f], We[f * NH + h], s);
        eb[e] = s;
    }
    __syncthreads();

    // scores 64x64, thread tile 4x8
    {
        const int i0 = (tid >> 3) * 4;
        const int j0 = (tid & 7) * 8;
        float acc[4][8];
#pragma unroll
        for (int i = 0; i < 4; i++)
#pragma unroll
            for (int j = 0; j < 8; j++) acc[i][j] = 0.f;

        for (int d = 0; d < 32; d++) {
            float a[4], b[8];
#pragma unroll
            for (int i = 0; i < 4; i++) a[i] = qs[i0 + i][d];
#pragma unroll
            for (int j = 0; j < 8; j++) b[j] = ks[j0 + j][d];
#pragma unroll
            for (int i = 0; i < 4; i++)
#pragma unroll
                for (int j = 0; j < 8; j++)
                    acc[i][j] = fmaf(a[i], b[j], acc[i][j]);
        }
#pragma unroll
        for (int i = 0; i < 4; i++)
#pragma unroll
            for (int j = 0; j < 8; j++)
                sc[i0 + i][j0 + j] = acc[i][j] * SCALE_F;
    }
    __syncthreads();

    // scatter edge bias (unique pairs -> no conflicts)
    for (int e = tid; e < EPG; e += 128) {
        const int ge = g * EPG + e;
        const int s  = senders[ge]   - g * 64;
        const int r  = receivers[ge] - g * 64;
        sc[r][s] += eb[e];
    }
    __syncthreads();

    // softmax over 64 keys, one warp per row
    {
        const int warp = tid >> 5;
        const int lane = tid & 31;
        for (int i = warp; i < 64; i += 4) {
            float x0 = sc[i][lane];
            float x1 = sc[i][lane + 32];
            float m = fmaxf(x0, x1);
#pragma unroll
            for (int o = 16; o > 0; o >>= 1)
                m = fmaxf(m, __shfl_xor_sync(0xffffffffu, m, o));
            float e0 = expf(x0 - m);
            float e1 = expf(x1 - m);
            float s = e0 + e1;
#pragma unroll
            for (int o = 16; o > 0; o >>= 1)
                s += __shfl_xor_sync(0xffffffffu, s, o);
            const float inv = 1.f / s;
            sc[i][lane]      = e0 * inv;
            sc[i][lane + 32] = e1 * inv;
        }
    }
    __syncthreads();

    // AV, thread tile 4x4 -> fp16 output
    {
        const int i0 = (tid >> 3) * 4;
        const int d0 = (tid & 7) * 4;
        float acc[4][4];
#pragma unroll
        for (int i = 0; i < 4; i++)
#pragma unroll
            for (int d = 0; d < 4; d++) acc[i][d] = 0.f;

        for (int j = 0; j < 64; j++) {
            float p[4], b[4];
#pragma unroll
            for (int i = 0; i < 4; i++) p[i] = sc[i0 + i][j];
#pragma unroll
            for (int d = 0; d < 4; d++) b[d] = vs[j][d0 + d];
#pragma unroll
            for (int i = 0; i < 4; i++)
#pragma unroll
                for (int d = 0; d < 4; d++)
                    acc[i][d] = fmaf(p[i], b[d], acc[i][d]);
        }
#pragma unroll
        for (int i = 0; i < 4; i++) {
            const int idx = (g * 64 + i0 + i) * 256 + h * 32 + d0;
            *(__half2*)&g_attn16[idx]     = __floats2half2_rn(acc[i][0], acc[i][1]);
            *(__half2*)&g_attn16[idx + 2] = __floats2half2_rn(acc[i][2], acc[i][3]);
        }
    }
}

// ---------------------------------------------------------------------------
extern "C" void kernel_launch(void* const* d_in, const int* in_sizes, int n_in,
                              void* d_out, int out_size)
{
    const float* nodes     = (const float*)d_in[0];
    const float* edges     = (const float*)d_in[1];
    const int*   senders   = (const int*)d_in[3];
    const int*   receivers = (const int*)d_in[4];
    const float* Wq = (const float*)d_in[5];
    const float* bq = (const float*)d_in[6];
    const float* Wk = (const float*)d_in[7];
    const float* bk = (const float*)d_in[8];
    const float* Wv = (const float*)d_in[9];
    const float* bv = (const float*)d_in[10];
    const float* Wo = (const float*)d_in[11];
    const float* bo = (const float*)d_in[12];
    const float* We = (const float*)d_in[13];
    const float* be = (const float*)d_in[14];
    float* out = (float*)d_out;

    cvt_kernel<<<512, dim3(32, 8)>>>(nodes, Wq, Wk, Wv, Wo);
    gemm_hmma_kernel<<<dim3(32, 6), 256>>>(bq, bk, bv, bo, out, 0);
    attn_kernel<<<GG * NH, 128>>>(senders, receivers, edges, We, be);
    gemm_hmma_kernel<<<dim3(32, 2), 256>>>(bq, bk, bv, bo, out, 1);
}

// round 7
// speedup vs baseline: 1.4208x; 1.4208x over previous
#include <cuda_runtime.h>
#include <cuda_fp16.h>
#include <mma.h>
#include <math.h>
#include <stdint.h>

using namespace nvcuda;

#define NN      2048
#define GG      32
#define NPG     64
#define EE      16384
#define EPG     512
#define HID     256
#define NH      8
#define HD      32
#define EF      16
#define SCALE_F 0.17677669529663687f   // 1/sqrt(32)

// ---------------- scratch (device globals, no runtime allocation) ----------
__device__ __align__(32) __half g_nodes16[NN * HID];
__device__ __align__(32) __half g_wT16[1024 * HID];   // rows 0-767: Wq|Wk|Wv cols, 768-1023: Wo cols (K contiguous)
__device__ __align__(32) __half g_attn16[NN * HID];
__device__ float g_q[NN * HID];
__device__ float g_k[NN * HID];
__device__ float g_v[NN * HID];

// ======================= cp.async helpers ==================================
__device__ __forceinline__ uint32_t smem_u32(const void* p) {
    uint32_t a;
    asm("{ .reg .u64 t; cvta.to.shared.u64 t, %1; cvt.u32.u64 %0, t; }" : "=r"(a) : "l"(p));
    return a;
}
__device__ __forceinline__ void cp_async16(void* sp, const void* gp) {
    asm volatile("cp.async.cg.shared.global [%0], [%1], 16;"
                 :: "r"(smem_u32(sp)), "l"(gp));
}
#define CP_COMMIT() asm volatile("cp.async.commit_group;" ::: "memory")
#define CP_WAIT1()  asm volatile("cp.async.wait_group 1;" ::: "memory")
#define CP_WAIT0()  asm volatile("cp.async.wait_group 0;" ::: "memory")

// ---------------------------------------------------------------------------
// Convert + transpose kernel (unchanged from R5).
// ---------------------------------------------------------------------------
__global__ void __launch_bounds__(256) cvt_kernel(
    const float* __restrict__ nodes,
    const float* __restrict__ Wq, const float* __restrict__ Wk,
    const float* __restrict__ Wv, const float* __restrict__ Wo)
{
    const int bx = blockIdx.x;
    const int tx = threadIdx.x;   // 0..31
    const int ty = threadIdx.y;   // 0..7
    if (bx < 256) {
        const int n0 = (bx & 31) * 32;
        const int k0 = (bx >> 5) * 32;
        __shared__ float s[32][33];
        const int mat  = n0 >> 8;
        const int col0 = n0 & 255;
        const float* W = (mat == 0) ? Wq : (mat == 1) ? Wk : (mat == 2) ? Wv : Wo;
#pragma unroll
        for (int j = 0; j < 4; j++) {
            const int k = k0 + ty + j * 8;
            s[ty + j * 8][tx] = W[k * 256 + col0 + tx];
        }
        __syncthreads();
#pragma unroll
        for (int j = 0; j < 4; j++) {
            const int n = n0 + ty + j * 8;
            g_wT16[n * 256 + k0 + tx] = __float2half(s[tx][ty + j * 8]);
        }
    } else {
        const int b   = bx - 256;
        const int tid = ty * 32 + tx;
#pragma unroll
        for (int r = 0; r < 2; r++) {
            const int i4 = b * 512 + r * 256 + tid;
            float4 v = ((const float4*)nodes)[i4];
            ((__half2*)g_nodes16)[i4 * 2 + 0] = __floats2half2_rn(v.x, v.y);
            ((__half2*)g_nodes16)[i4 * 2 + 1] = __floats2half2_rn(v.z, v.w);
        }
    }
}

// ---------------------------------------------------------------------------
// Pipelined HMMA GEMM: C[m0:m0+64, n-range 64] = A16 @ B16^T + bias.
// 64x64 tile, 128 threads (4 warps, 2x2 warp grid, warp tile 32x32).
// K chunked at 64, double-buffered cp.async staging of A and B.
// ---------------------------------------------------------------------------
static constexpr int LDT = 72;   // smem tile ld (halves), pad 8

__global__ void __launch_bounds__(128) gemm_hmma_kernel(
    const float* __restrict__ bq, const float* __restrict__ bk,
    const float* __restrict__ bv, const float* __restrict__ bo,
    float* __restrict__ outp, int pass)
{
    const int m0 = blockIdx.x * 64;
    const int by = blockIdx.y;
    const __half* Asrc;
    const float* bias;
    float* C;
    int wrow0;
    if (pass == 0) {                // QKV: by 0..11
        const int which = by >> 2;
        const int colin = (by & 3) * 64;
        Asrc  = g_nodes16;
        wrow0 = by * 64;
        C     = ((which == 0) ? g_q : (which == 1) ? g_k : g_v) + colin;
        bias  = ((which == 0) ? bq : (which == 1) ? bk : bv) + colin;
    } else {                        // out-proj: by 0..3
        Asrc  = g_attn16;
        wrow0 = 768 + by * 64;
        C     = outp + by * 64;
        bias  = bo + by * 64;
    }

    __shared__ __align__(32) __half As[2][64][LDT];
    __shared__ __align__(32) __half Bs[2][64][LDT];

    const int tid  = threadIdx.x;   // 0..127
    const int wid  = tid >> 5;
    const int wr   = (wid >> 1) * 32;   // 0 or 32
    const int wc   = (wid & 1) * 32;    // 0 or 32

    const __half* Ab = Asrc + m0 * 256;
    const __half* Bb = g_wT16 + wrow0 * 256;

    // thread's staging slots: 512 uint4 per matrix per chunk, 4 per thread
    const int srow = tid >> 1;                 // 0..63  (2 threads/row, 4 rows... )
    // simpler mapping: idx = tid + t*128 -> row = idx>>3, q = idx&7
    auto load_chunk = [&](int c, int buf) {
#pragma unroll
        for (int t = 0; t < 4; t++) {
            const int idx = tid + t * 128;     // 0..511
            const int r = idx >> 3, q = (idx & 7) * 8;
            cp_async16(&As[buf][r][q], Ab + r * 256 + c * 64 + q);
            cp_async16(&Bs[buf][r][q], Bb + r * 256 + c * 64 + q);
        }
        CP_COMMIT();
    };
    (void)srow;

    wmma::fragment<wmma::accumulator, 16, 16, 16, float> fc[2][2];
#pragma unroll
    for (int i = 0; i < 2; i++)
#pragma unroll
        for (int j = 0; j < 2; j++) wmma::fill_fragment(fc[i][j], 0.0f);

    load_chunk(0, 0);
#pragma unroll
    for (int c = 0; c < 4; c++) {
        if (c + 1 < 4) { load_chunk(c + 1, (c + 1) & 1); CP_WAIT1(); }
        else           { CP_WAIT0(); }
        __syncthreads();
        const int buf = c & 1;
#pragma unroll
        for (int kk = 0; kk < 64; kk += 16) {
            wmma::fragment<wmma::matrix_a, 16, 16, 16, __half, wmma::row_major> fa[2];
            wmma::fragment<wmma::matrix_b, 16, 16, 16, __half, wmma::col_major> fb[2];
#pragma unroll
            for (int i = 0; i < 2; i++)
                wmma::load_matrix_sync(fa[i], &As[buf][wr + i * 16][kk], LDT);
#pragma unroll
            for (int j = 0; j < 2; j++)
                wmma::load_matrix_sync(fb[j], &Bs[buf][wc + j * 16][kk], LDT);
#pragma unroll
            for (int i = 0; i < 2; i++)
#pragma unroll
                for (int j = 0; j < 2; j++)
                    wmma::mma_sync(fc[i][j], fa[i], fb[j], fc[i][j]);
        }
        __syncthreads();
    }

    // ---- epilogue through smem (reuse As/Bs), bias add, vector store ----
    float* Cs = (float*)&As[0][0][0];   // 64 x 68 floats = 17408 B < 18432 B
#pragma unroll
    for (int i = 0; i < 2; i++)
#pragma unroll
        for (int j = 0; j < 2; j++)
            wmma::store_matrix_sync(&Cs[(wr + i * 16) * 68 + wc + j * 16],
                                    fc[i][j], 68, wmma::mem_row_major);
    __syncthreads();

#pragma unroll
    for (int i = tid; i < 1024; i += 128) {     // 64 rows x 16 float4
        const int r = i >> 4, c4 = (i & 15) * 4;
        float4 v = *(float4*)&Cs[r * 68 + c4];
        v.x += bias[c4 + 0];
        v.y += bias[c4 + 1];
        v.z += bias[c4 + 2];
        v.w += bias[c4 + 3];
        *(float4*)&C[(m0 + r) * 256 + c4] = v;
    }
}

// ---------------------------------------------------------------------------
// K2: per-(graph, head) attention, now 256 threads/block.
// ---------------------------------------------------------------------------
__global__ void __launch_bounds__(256) attn_kernel(
    const int* __restrict__ senders,
    const int* __restrict__ receivers,
    const float* __restrict__ edges,
    const float* __restrict__ We,
    const float* __restrict__ be)
{
    const int g = blockIdx.x >> 3;
    const int h = blockIdx.x & 7;
    const int tid = threadIdx.x;    // 0..255

    __shared__ float qs[64][33];
    __shared__ float ks[64][33];
    __shared__ float vs[64][33];
    __shared__ float sc[64][65];
    __shared__ float eb[EPG];

    for (int idx = tid; idx < 64 * 32; idx += 256) {
        const int r = idx >> 5;
        const int c = idx & 31;
        const int ga = (g * 64 + r) * 256 + h * 32 + c;
        qs[r][c] = g_q[ga];
        ks[r][c] = g_k[ga];
        vs[r][c] = g_v[ga];
    }

    for (int e = tid; e < EPG; e += 256) {
        const float* ef = &edges[(g * EPG + e) * EF];
        float s = be[h];
#pragma unroll
        for (int f = 0; f < EF; f++) s = fmaf(ef[f], We[f * NH + h], s);
        eb[e] = s;
    }
    __syncthreads();

    // scores 64x64: 16x16 thread grid, each 4x4
    {
        const int i0 = (tid >> 4) * 4;
        const int j0 = (tid & 15) * 4;
        float acc[4][4];
#pragma unroll
        for (int i = 0; i < 4; i++)
#pragma unroll
            for (int j = 0; j < 4; j++) acc[i][j] = 0.f;

        for (int d = 0; d < 32; d++) {
            float a[4], b[4];
#pragma unroll
            for (int i = 0; i < 4; i++) a[i] = qs[i0 + i][d];
#pragma unroll
            for (int j = 0; j < 4; j++) b[j] = ks[j0 + j][d];
#pragma unroll
            for (int i = 0; i < 4; i++)
#pragma unroll
                for (int j = 0; j < 4; j++)
                    acc[i][j] = fmaf(a[i], b[j], acc[i][j]);
        }
#pragma unroll
        for (int i = 0; i < 4; i++)
#pragma unroll
            for (int j = 0; j < 4; j++)
                sc[i0 + i][j0 + j] = acc[i][j] * SCALE_F;
    }
    __syncthreads();

    // scatter edge bias (unique pairs -> no conflicts)
    for (int e = tid; e < EPG; e += 256) {
        const int ge = g * EPG + e;
        const int s  = senders[ge]   - g * 64;
        const int r  = receivers[ge] - g * 64;
        sc[r][s] += eb[e];
    }
    __syncthreads();

    // softmax over 64 keys, one warp per row, 8 warps
    {
        const int warp = tid >> 5;
        const int lane = tid & 31;
        for (int i = warp; i < 64; i += 8) {
            float x0 = sc[i][lane];
            float x1 = sc[i][lane + 32];
            float m = fmaxf(x0, x1);
#pragma unroll
            for (int o = 16; o > 0; o >>= 1)
                m = fmaxf(m, __shfl_xor_sync(0xffffffffu, m, o));
            float e0 = expf(x0 - m);
            float e1 = expf(x1 - m);
            float s = e0 + e1;
#pragma unroll
            for (int o = 16; o > 0; o >>= 1)
                s += __shfl_xor_sync(0xffffffffu, s, o);
            const float inv = 1.f / s;
            sc[i][lane]      = e0 * inv;
            sc[i][lane + 32] = e1 * inv;
        }
    }
    __syncthreads();

    // AV: 64x32 out, thread tile 2 rows x 4 cols -> fp16
    {
        const int i0 = (tid >> 3) * 2;
        const int d0 = (tid & 7) * 4;
        float acc[2][4];
#pragma unroll
        for (int i = 0; i < 2; i++)
#pragma unroll
            for (int d = 0; d < 4; d++) acc[i][d] = 0.f;

        for (int j = 0; j < 64; j++) {
            float p0 = sc[i0][j], p1 = sc[i0 + 1][j];
            float b[4];
#pragma unroll
            for (int d = 0; d < 4; d++) b[d] = vs[j][d0 + d];
#pragma unroll
            for (int d = 0; d < 4; d++) {
                acc[0][d] = fmaf(p0, b[d], acc[0][d]);
                acc[1][d] = fmaf(p1, b[d], acc[1][d]);
            }
        }
#pragma unroll
        for (int i = 0; i < 2; i++) {
            const int idx = (g * 64 + i0 + i) * 256 + h * 32 + d0;
            *(__half2*)&g_attn16[idx]     = __floats2half2_rn(acc[i][0], acc[i][1]);
            *(__half2*)&g_attn16[idx + 2] = __floats2half2_rn(acc[i][2], acc[i][3]);
        }
    }
}

// ---------------------------------------------------------------------------
extern "C" void kernel_launch(void* const* d_in, const int* in_sizes, int n_in,
                              void* d_out, int out_size)
{
    const float* nodes     = (const float*)d_in[0];
    const float* edges     = (const float*)d_in[1];
    const int*   senders   = (const int*)d_in[3];
    const int*   receivers = (const int*)d_in[4];
    const float* Wq = (const float*)d_in[5];
    const float* bq = (const float*)d_in[6];
    const float* Wk = (const float*)d_in[7];
    const float* bk = (const float*)d_in[8];
    const float* Wv = (const float*)d_in[9];
    const float* bv = (const float*)d_in[10];
    const float* Wo = (const float*)d_in[11];
    const float* bo = (const float*)d_in[12];
    const float* We = (const float*)d_in[13];
    const float* be = (const float*)d_in[14];
    float* out = (float*)d_out;

    cvt_kernel<<<512, dim3(32, 8)>>>(nodes, Wq, Wk, Wv, Wo);
    gemm_hmma_kernel<<<dim3(32, 12), 128>>>(bq, bk, bv, bo, out, 0);
    attn_kernel<<<GG * NH, 256>>>(senders, receivers, edges, We, be);
    gemm_hmma_kernel<<<dim3(32, 4), 128>>>(bq, bk, bv, bo, out, 1);
}